// round 15
// baseline (speedup 1.0000x reference)
#include <cuda_runtime.h>
#include <cuda_fp16.h>
#include <cstdint>

#define TT 512
#define BATCH 128
#define IND 128
#define HH 1024
#define OUTD 64
#define NCTA 130
#define NTHR 256
#define NKS 72

#define OFF_BIAS 0
#define OFF_BFRAG 1024
#define BFRAG_SZ (NKS * 2 * 32 * 16)            // 73728 (f16, 2 nt per uint4)
#define SMEM_TOTAL (OFF_BFRAG + BFRAG_SZ)       // 74752

// A operands pre-packed in mma m16n8k16 fragment order, SINGLE f16:
// entry [..][mg][s][lane] = uint4(a0,a1,a2,a3); a0=(r,k,k+1) a1=(r+8,·)
// a2=(r,k+8,k+9) a3=(r+8,·), r=16mg+(lane>>2), k=16s+(lane&3)*2.
__device__ uint4 g_uf[(size_t)TT * 8 * 8 * 32];       // [t][mg][s0..7][lane]
__device__ uint4 g_hf[2 * 8 * 64 * 32];               // [ph][mg][hs0..63][lane]
__device__ unsigned int g_bar_count = 0;
__device__ unsigned int g_bar_gen = 0;

__device__ __forceinline__ float sg(float x) { return __fdividef(1.0f, 1.0f + __expf(-x)); }
__device__ __forceinline__ float th(float x) { return __fdividef(2.0f, 1.0f + __expf(-2.0f * x)) - 1.0f; }

__device__ __forceinline__ uint32_t pkf16s(float a, float b) {
    return (uint32_t)__half_as_ushort(__float2half_rn(a))
         | ((uint32_t)__half_as_ushort(__float2half_rn(b)) << 16);
}

__device__ __forceinline__ void mma_f16(float* d, const uint32_t* a, uint32_t b0, uint32_t b1) {
    asm volatile(
        "mma.sync.aligned.m16n8k16.row.col.f32.f16.f16.f32 "
        "{%0,%1,%2,%3}, {%4,%5,%6,%7}, {%8,%9}, {%0,%1,%2,%3};"
        : "+f"(d[0]), "+f"(d[1]), "+f"(d[2]), "+f"(d[3])
        : "r"(a[0]), "r"(a[1]), "r"(a[2]), "r"(a[3]), "r"(b0), "r"(b1));
}

__device__ __forceinline__ void grid_barrier_full(unsigned int& epoch) {
    __syncthreads();
    if (threadIdx.x == 0) {
        __threadfence();
        unsigned int target = epoch + 1;
        unsigned int arr = atomicAdd(&g_bar_count, 1u);
        if (arr == NCTA - 1) {
            atomicExch(&g_bar_count, 0u);
            __threadfence();
            atomicAdd(&g_bar_gen, 1u);
        } else {
            while ((int)(*(volatile unsigned int*)&g_bar_gen - target) < 0) __nanosleep(32);
        }
        epoch = target;
        __threadfence();
    }
    __syncthreads();
}

__device__ __forceinline__ void bar_arrive() {
    if (threadIdx.x == 0) {
        __threadfence();
        unsigned int arr = atomicAdd(&g_bar_count, 1u);
        if (arr == NCTA - 1) {
            atomicExch(&g_bar_count, 0u);
            __threadfence();
            atomicAdd(&g_bar_gen, 1u);
        }
    }
}
__device__ __forceinline__ void bar_wait(unsigned int target) {
    while ((int)(*(volatile unsigned int*)&g_bar_gen - target) < 0) { }
    __threadfence();
}

// load chunk c's 4 fragment ksteps. tu = u timestep (chunks 0,1);
// hp = h buffer phase (chunks >= 2) — distinct on drain step t=TT.
__device__ __forceinline__ void load_chunk(int tu, int hp, int c, int mg, int lane,
                                           uint4* fh)
{
    const uint4* ph;
    if (c < 2) {
        ph = g_uf + (((size_t)tu * 8 + mg) * 8 + c * 4) * 32 + lane;
    } else {
        ph = g_hf + (((size_t)hp * 8 + mg) * 64 + (c * 4 - 8)) * 32 + lane;
    }
    #pragma unroll
    for (int i = 0; i < 4; ++i) fh[i] = __ldcg(ph + i * 32);
}

// 1-pass f16: A*B; B f16, 2 nt per uint4. Even kk -> acc0, odd kk -> acc1
// (two independent accumulator chains per nt to double tensor-pipe ILP).
__device__ __forceinline__ void compute_chunk(int c, const uint4* fh,
                                              float acc0[4][4], float acc1[4][4],
                                              const char* bf, int lane)
{
    #pragma unroll
    for (int kk = 0; kk < 4; ++kk) {
        const uint32_t* a = (const uint32_t*)&fh[kk];
        int s = c * 4 + kk;
        float (*acc)[4] = (kk & 1) ? acc1 : acc0;
        #pragma unroll
        for (int ntp = 0; ntp < 2; ++ntp) {
            uint4 bb = *(const uint4*)(bf + (uint32_t)((s * 2 + ntp) * 32 + lane) * 16);
            mma_f16(acc[2 * ntp + 0], a, bb.x, bb.y);
            mma_f16(acc[2 * ntp + 1], a, bb.z, bb.w);
        }
    }
}

__global__ void __launch_bounds__(NTHR, 1)
lstm_mma(const float* __restrict__ u, const float* __restrict__ x0,
         const float* __restrict__ kfiz, const float* __restrict__ bfiz,
         const float* __restrict__ kr, const float* __restrict__ br,
         const float* __restrict__ wout, const float* __restrict__ bout,
         float* __restrict__ y)
{
    extern __shared__ char smem[];
    const int tid = threadIdx.x;
    const int bid = blockIdx.x;
    const int mg = tid >> 5, lane = tid & 31;     // 8 warps = 8 row groups
    const int gid = lane >> 2, tig = lane & 3;
    float* bias_s = (float*)(smem + OFF_BIAS);
    unsigned int* base_s = (unsigned int*)(smem + OFF_BIAS + 512);

    // ---- init: weights -> smem B fragments (f16, 2 nt per uint4) ----
    for (int idx = tid; idx < NKS * 2 * 32; idx += NTHR) {
        int l = idx & 31;
        int ntp = (idx >> 5) & 1;
        int s = idx >> 6;
        uint32_t r[4];
        #pragma unroll
        for (int half = 0; half < 2; ++half) {
            int nt = ntp * 2 + half;
            int nloc = nt * 8 + (l >> 2);
            int k0 = s * 16 + (l & 3) * 2;
            float w[4];
            #pragma unroll
            for (int q = 0; q < 4; ++q) {
                int k = k0 + (q >> 1) * 8 + (q & 1);
                float v;
                if (bid < 128) {
                    int g = nloc >> 3, hid = bid * 8 + (nloc & 7);
                    v = (g < 3) ? kfiz[(size_t)k * 3072 + g * 1024 + hid]
                                : kr[(size_t)k * 1024 + hid];
                } else {
                    int col = (bid - 128) * 32 + nloc;
                    v = (k < IND) ? 0.0f : wout[(size_t)(k - IND) * OUTD + col];
                }
                w[q] = v;
            }
            r[half * 2 + 0] = pkf16s(w[0], w[1]);
            r[half * 2 + 1] = pkf16s(w[2], w[3]);
        }
        *(uint4*)(smem + OFF_BFRAG + (uint32_t)idx * 16) = make_uint4(r[0], r[1], r[2], r[3]);
    }
    if (tid < 32) {
        float bv;
        if (bid < 128) {
            int g = tid >> 3, hid = bid * 8 + (tid & 7);
            bv = (g < 3) ? bfiz[g * 1024 + hid] : br[hid];
        } else bv = bout[(bid - 128) * 32 + tid];
        bias_s[tid] = bv;
    }

    // ---- init: u -> fragment layout (single f16, grid-strided) ----
    {
        const size_t UN = (size_t)TT * 8 * 8 * 32;
        for (size_t e = (size_t)bid * NTHR + tid; e < UN; e += (size_t)NCTA * NTHR) {
            int el = (int)(e & 31);
            int es = (int)((e >> 5) & 7);
            int emg = (int)((e >> 8) & 7);
            int et = (int)(e >> 11);
            int r = emg * 16 + (el >> 2);
            int k = es * 16 + (el & 3) * 2;
            const float* u0 = u + ((size_t)r * TT + et) * IND + k;
            const float* u8 = u + ((size_t)(r + 8) * TT + et) * IND + k;
            g_uf[e] = make_uint4(pkf16s(u0[0], u0[1]), pkf16s(u8[0], u8[1]),
                                 pkf16s(u0[8], u0[9]), pkf16s(u8[8], u8[9]));
        }
    }

    // ---- init: c0 (registers), h0 -> fragment layout, phase 0 ----
    const int r0 = mg * 16 + gid, r1 = r0 + 8;
    float creg[4];
    if (bid < 128) {
        creg[0] = x0[(size_t)r0 * 2 * HH + HH + bid * 8 + tig * 2];
        creg[1] = x0[(size_t)r0 * 2 * HH + HH + bid * 8 + tig * 2 + 1];
        creg[2] = x0[(size_t)r1 * 2 * HH + HH + bid * 8 + tig * 2];
        creg[3] = x0[(size_t)r1 * 2 * HH + HH + bid * 8 + tig * 2 + 1];
        float hv0 = x0[(size_t)r0 * 2 * HH + bid * 8 + tig * 2];
        float hv1 = x0[(size_t)r0 * 2 * HH + bid * 8 + tig * 2 + 1];
        float hv2 = x0[(size_t)r1 * 2 * HH + bid * 8 + tig * 2];
        float hv3 = x0[(size_t)r1 * 2 * HH + bid * 8 + tig * 2 + 1];
        size_t eo = (((size_t)mg * 64 + (bid >> 1)) * 32 + lane) * 16 + (size_t)(bid & 1) * 8;
        __stcg((uint2*)((char*)g_hf + eo), make_uint2(pkf16s(hv0, hv1), pkf16s(hv2, hv3)));
    }

    unsigned int epoch = 0;
    if (tid == 0) epoch = *(volatile unsigned int*)&g_bar_gen;
    grid_barrier_full(epoch);
    if (tid == 0) *base_s = epoch;
    __syncthreads();
    const unsigned int base = *base_s;

    float bcol[4][2];
    #pragma unroll
    for (int nt = 0; nt < 4; ++nt) {
        bcol[nt][0] = bias_s[nt * 8 + tig * 2];
        bcol[nt][1] = bias_s[nt * 8 + tig * 2 + 1];
    }

    const char* bf = smem + OFF_BFRAG;
    const size_t hstore0 = (((size_t)mg * 64 + (bid >> 1)) * 32 + lane) * 16
                         + (size_t)(bid & 1) * 8;

    // depth-3 register staging: chunk c lives in buffer c%3 (18%3==0 ->
    // ring position is step-invariant)
    uint4 fh[3][4];
    load_chunk(0, 0, 0, mg, lane, fh[0]);
    load_chunk(0, 0, 1, mg, lane, fh[1]);

    for (int t = 0; t <= TT; ++t) {
        const int tt = (t < TT) ? t : (TT - 1);   // u timestep (clamped)
        const int hp = t & 1;                     // h buffer phase (NOT clamped)

        float acc0[4][4], acc1[4][4];
        #pragma unroll
        for (int nt = 0; nt < 4; ++nt)
            #pragma unroll
            for (int q = 0; q < 4; ++q) { acc0[nt][q] = 0.0f; acc1[nt][q] = 0.0f; }

        compute_chunk(0, fh[0], acc0, acc1, bf, lane);
        bar_wait(base + t);                       // h(t) published
        load_chunk(tt, hp, 2, mg, lane, fh[2]);

        #pragma unroll
        for (int c = 1; c < 18; ++c) {
            if (c <= 15) {
                load_chunk(tt, hp, c + 2, mg, lane, fh[(c + 2) % 3]);
            } else if (t < TT) {
                int tn = (t + 1 < TT) ? (t + 1) : (TT - 1);
                load_chunk(tn, 0, c - 16, mg, lane, fh[(c + 2) % 3]);
            }
            compute_chunk(c, fh[c % 3], acc0, acc1, bf, lane);
        }

        // ---- warp-local epilogue (merge the two accumulator chains) ----
        if (bid < 128) {
            if (t < TT) {
                float hv[4];
                #pragma unroll
                for (int q = 0; q < 4; ++q) {
                    int e = q & 1;
                    float fp = (acc0[0][q] + acc1[0][q]) + bcol[0][e];
                    float ip = (acc0[1][q] + acc1[1][q]) + bcol[1][e];
                    float zp = (acc0[2][q] + acc1[2][q]) + bcol[2][e];
                    float rp = (acc0[3][q] + acc1[3][q]) + bcol[3][e];
                    creg[q] = sg(fp) * creg[q] + sg(ip) * th(rp);
                    hv[q] = sg(zp) * th(creg[q]);
                }
                size_t eo = hstore0 + (size_t)((t + 1) & 1) * (8 * 64 * 32 * 16);
                __stcg((uint2*)((char*)g_hf + eo),
                       make_uint2(pkf16s(hv[0], hv[1]), pkf16s(hv[2], hv[3])));
            }
        } else if (t >= 1) {
            #pragma unroll
            for (int nt = 0; nt < 4; ++nt) {
                int gcol = (bid - 128) * 32 + nt * 8 + tig * 2;
                float2 v0 = make_float2((acc0[nt][0] + acc1[nt][0]) + bcol[nt][0],
                                        (acc0[nt][1] + acc1[nt][1]) + bcol[nt][1]);
                float2 v1 = make_float2((acc0[nt][2] + acc1[nt][2]) + bcol[nt][0],
                                        (acc0[nt][3] + acc1[nt][3]) + bcol[nt][1]);
                *(float2*)&y[((size_t)r0 * TT + (t - 1)) * OUTD + gcol] = v0;
                *(float2*)&y[((size_t)r1 * TT + (t - 1)) * OUTD + gcol] = v1;
            }
        }

        __syncthreads();        // all warps' h stores done before arrival
        bar_arrive();           // non-blocking; wait deferred into next step
    }
}

extern "C" void kernel_launch(void* const* d_in, const int* in_sizes, int n_in,
                              void* d_out, int out_size) {
    (void)in_sizes; (void)n_in; (void)out_size;
    cudaFuncSetAttribute(lstm_mma, cudaFuncAttributeMaxDynamicSharedMemorySize, SMEM_TOTAL);
    lstm_mma<<<NCTA, NTHR, SMEM_TOTAL>>>(
        (const float*)d_in[0], (const float*)d_in[1], (const float*)d_in[2],
        (const float*)d_in[3], (const float*)d_in[4], (const float*)d_in[5],
        (const float*)d_in[6], (const float*)d_in[7], (float*)d_out);
}

// round 17
// speedup vs baseline: 1.0958x; 1.0958x over previous
#include <cuda_runtime.h>
#include <cuda_fp16.h>
#include <cstdint>

#define TT 512
#define BATCH 128
#define IND 128
#define HH 1024
#define OUTD 64
#define NCTA 130
#define NTHR 256
#define NKS 72

#define OFF_BIAS 0
#define OFF_BFRAG 1024
#define BFRAG_SZ (NKS * 2 * 32 * 16)            // 73728 (f16, 2 nt per uint4)
#define SMEM_TOTAL (OFF_BFRAG + BFRAG_SZ)       // 74752

// A operands pre-packed in mma m16n8k16 fragment order, SINGLE f16:
// entry [..][mg][s][lane] = uint4(a0,a1,a2,a3); a0=(r,k,k+1) a1=(r+8,·)
// a2=(r,k+8,k+9) a3=(r+8,·), r=16mg+(lane>>2), k=16s+(lane&3)*2.
__device__ uint4 g_uf[(size_t)TT * 8 * 8 * 32];       // [t][mg][s0..7][lane]
__device__ uint4 g_hf[2 * 8 * 64 * 32];               // [ph][mg][hs0..63][lane]
__device__ unsigned int g_bar_count = 0;              // init barrier only
__device__ unsigned int g_bar_gen = 0;                // init barrier only
__device__ unsigned int g_step_count = 0;             // monotonic per-step counter

__device__ __forceinline__ float sg(float x) { return __fdividef(1.0f, 1.0f + __expf(-x)); }
__device__ __forceinline__ float th(float x) { return __fdividef(2.0f, 1.0f + __expf(-2.0f * x)) - 1.0f; }

__device__ __forceinline__ uint32_t pkf16s(float a, float b) {
    return (uint32_t)__half_as_ushort(__float2half_rn(a))
         | ((uint32_t)__half_as_ushort(__float2half_rn(b)) << 16);
}

__device__ __forceinline__ void mma_f16(float* d, const uint32_t* a, uint32_t b0, uint32_t b1) {
    asm volatile(
        "mma.sync.aligned.m16n8k16.row.col.f32.f16.f16.f32 "
        "{%0,%1,%2,%3}, {%4,%5,%6,%7}, {%8,%9}, {%0,%1,%2,%3};"
        : "+f"(d[0]), "+f"(d[1]), "+f"(d[2]), "+f"(d[3])
        : "r"(a[0]), "r"(a[1]), "r"(a[2]), "r"(a[3]), "r"(b0), "r"(b1));
}

// init-only classic barrier (gen/count pair, self-resetting)
__device__ __forceinline__ void grid_barrier_full() {
    __syncthreads();
    if (threadIdx.x == 0) {
        __threadfence();
        unsigned int epoch = *(volatile unsigned int*)&g_bar_gen;
        unsigned int target = epoch + 1;
        unsigned int arr = atomicAdd(&g_bar_count, 1u);
        if (arr == NCTA - 1) {
            atomicExch(&g_bar_count, 0u);
            __threadfence();
            atomicAdd(&g_bar_gen, 1u);
        } else {
            while ((int)(*(volatile unsigned int*)&g_bar_gen - target) < 0) __nanosleep(32);
        }
        __threadfence();
    }
    __syncthreads();
}

// per-step arrival: return-free RED (no atomic-return serialization)
__device__ __forceinline__ void bar_arrive() {
    if (threadIdx.x == 0) {
        __threadfence();
        asm volatile("red.global.add.u32 [%0], %1;" :: "l"(&g_step_count), "r"(1u) : "memory");
    }
}
// wait until all NCTA arrivals of steps < t have posted
__device__ __forceinline__ void bar_wait(unsigned int t) {
    const unsigned int target = (unsigned int)NCTA * t;
    while ((int)(*(volatile unsigned int*)&g_step_count - target) < 0) { }
    __threadfence();
}

// load chunk c's 4 fragment ksteps. tu = u timestep (chunks 0,1);
// hp = h buffer phase (chunks >= 2) — distinct on drain step t=TT.
__device__ __forceinline__ void load_chunk(int tu, int hp, int c, int mg, int lane,
                                           uint4* fh)
{
    const uint4* ph;
    if (c < 2) {
        ph = g_uf + (((size_t)tu * 8 + mg) * 8 + c * 4) * 32 + lane;
    } else {
        ph = g_hf + (((size_t)hp * 8 + mg) * 64 + (c * 4 - 8)) * 32 + lane;
    }
    #pragma unroll
    for (int i = 0; i < 4; ++i) fh[i] = __ldcg(ph + i * 32);
}

// 1-pass f16: A*B; B f16, 2 nt per uint4
__device__ __forceinline__ void compute_chunk(int c, const uint4* fh,
                                              float acc[4][4], const char* bf, int lane)
{
    #pragma unroll
    for (int kk = 0; kk < 4; ++kk) {
        const uint32_t* a = (const uint32_t*)&fh[kk];
        int s = c * 4 + kk;
        #pragma unroll
        for (int ntp = 0; ntp < 2; ++ntp) {
            uint4 bb = *(const uint4*)(bf + (uint32_t)((s * 2 + ntp) * 32 + lane) * 16);
            mma_f16(acc[2 * ntp + 0], a, bb.x, bb.y);
            mma_f16(acc[2 * ntp + 1], a, bb.z, bb.w);
        }
    }
}

__global__ void __launch_bounds__(NTHR, 1)
lstm_mma(const float* __restrict__ u, const float* __restrict__ x0,
         const float* __restrict__ kfiz, const float* __restrict__ bfiz,
         const float* __restrict__ kr, const float* __restrict__ br,
         const float* __restrict__ wout, const float* __restrict__ bout,
         float* __restrict__ y)
{
    extern __shared__ char smem[];
    const int tid = threadIdx.x;
    const int bid = blockIdx.x;
    const int mg = tid >> 5, lane = tid & 31;     // 8 warps = 8 row groups
    const int gid = lane >> 2, tig = lane & 3;
    float* bias_s = (float*)(smem + OFF_BIAS);

    // reset monotonic step counter (graph replays reuse device globals);
    // ordered before everyone's first per-step arrival by the init barrier
    if (bid == 0 && tid == 0) *(volatile unsigned int*)&g_step_count = 0u;

    // ---- init: weights -> smem B fragments (f16, 2 nt per uint4) ----
    for (int idx = tid; idx < NKS * 2 * 32; idx += NTHR) {
        int l = idx & 31;
        int ntp = (idx >> 5) & 1;
        int s = idx >> 6;
        uint32_t r[4];
        #pragma unroll
        for (int half = 0; half < 2; ++half) {
            int nt = ntp * 2 + half;
            int nloc = nt * 8 + (l >> 2);
            int k0 = s * 16 + (l & 3) * 2;
            float w[4];
            #pragma unroll
            for (int q = 0; q < 4; ++q) {
                int k = k0 + (q >> 1) * 8 + (q & 1);
                float v;
                if (bid < 128) {
                    int g = nloc >> 3, hid = bid * 8 + (nloc & 7);
                    v = (g < 3) ? kfiz[(size_t)k * 3072 + g * 1024 + hid]
                                : kr[(size_t)k * 1024 + hid];
                } else {
                    int col = (bid - 128) * 32 + nloc;
                    v = (k < IND) ? 0.0f : wout[(size_t)(k - IND) * OUTD + col];
                }
                w[q] = v;
            }
            r[half * 2 + 0] = pkf16s(w[0], w[1]);
            r[half * 2 + 1] = pkf16s(w[2], w[3]);
        }
        *(uint4*)(smem + OFF_BFRAG + (uint32_t)idx * 16) = make_uint4(r[0], r[1], r[2], r[3]);
    }
    if (tid < 32) {
        float bv;
        if (bid < 128) {
            int g = tid >> 3, hid = bid * 8 + (tid & 7);
            bv = (g < 3) ? bfiz[g * 1024 + hid] : br[hid];
        } else bv = bout[(bid - 128) * 32 + tid];
        bias_s[tid] = bv;
    }

    // ---- init: u -> fragment layout (single f16, grid-strided) ----
    {
        const size_t UN = (size_t)TT * 8 * 8 * 32;
        for (size_t e = (size_t)bid * NTHR + tid; e < UN; e += (size_t)NCTA * NTHR) {
            int el = (int)(e & 31);
            int es = (int)((e >> 5) & 7);
            int emg = (int)((e >> 8) & 7);
            int et = (int)(e >> 11);
            int r = emg * 16 + (el >> 2);
            int k = es * 16 + (el & 3) * 2;
            const float* u0 = u + ((size_t)r * TT + et) * IND + k;
            const float* u8 = u + ((size_t)(r + 8) * TT + et) * IND + k;
            g_uf[e] = make_uint4(pkf16s(u0[0], u0[1]), pkf16s(u8[0], u8[1]),
                                 pkf16s(u0[8], u0[9]), pkf16s(u8[8], u8[9]));
        }
    }

    // ---- init: c0 (registers), h0 -> fragment layout, phase 0 ----
    const int r0 = mg * 16 + gid, r1 = r0 + 8;
    float creg[4];
    if (bid < 128) {
        creg[0] = x0[(size_t)r0 * 2 * HH + HH + bid * 8 + tig * 2];
        creg[1] = x0[(size_t)r0 * 2 * HH + HH + bid * 8 + tig * 2 + 1];
        creg[2] = x0[(size_t)r1 * 2 * HH + HH + bid * 8 + tig * 2];
        creg[3] = x0[(size_t)r1 * 2 * HH + HH + bid * 8 + tig * 2 + 1];
        float hv0 = x0[(size_t)r0 * 2 * HH + bid * 8 + tig * 2];
        float hv1 = x0[(size_t)r0 * 2 * HH + bid * 8 + tig * 2 + 1];
        float hv2 = x0[(size_t)r1 * 2 * HH + bid * 8 + tig * 2];
        float hv3 = x0[(size_t)r1 * 2 * HH + bid * 8 + tig * 2 + 1];
        size_t eo = (((size_t)mg * 64 + (bid >> 1)) * 32 + lane) * 16 + (size_t)(bid & 1) * 8;
        __stcg((uint2*)((char*)g_hf + eo), make_uint2(pkf16s(hv0, hv1), pkf16s(hv2, hv3)));
    }

    grid_barrier_full();    // init data + counter reset globally visible

    float bcol[4][2];
    #pragma unroll
    for (int nt = 0; nt < 4; ++nt) {
        bcol[nt][0] = bias_s[nt * 8 + tig * 2];
        bcol[nt][1] = bias_s[nt * 8 + tig * 2 + 1];
    }

    const char* bf = smem + OFF_BFRAG;
    const size_t hstore0 = (((size_t)mg * 64 + (bid >> 1)) * 32 + lane) * 16
                         + (size_t)(bid & 1) * 8;

    // depth-3 register staging: chunk c lives in buffer c%3 (18%3==0 ->
    // ring position is step-invariant)
    uint4 fh[3][4];
    load_chunk(0, 0, 0, mg, lane, fh[0]);
    load_chunk(0, 0, 1, mg, lane, fh[1]);

    for (int t = 0; t <= TT; ++t) {
        const int tt = (t < TT) ? t : (TT - 1);   // u timestep (clamped)
        const int hp = t & 1;                     // h buffer phase (NOT clamped)

        float acc[4][4];
        #pragma unroll
        for (int nt = 0; nt < 4; ++nt)
            #pragma unroll
            for (int q = 0; q < 4; ++q) acc[nt][q] = 0.0f;

        compute_chunk(0, fh[0], acc, bf, lane);
        bar_wait((unsigned int)t);                // h(t) published
        load_chunk(tt, hp, 2, mg, lane, fh[2]);

        #pragma unroll
        for (int c = 1; c < 18; ++c) {
            if (c <= 15) {
                load_chunk(tt, hp, c + 2, mg, lane, fh[(c + 2) % 3]);
            } else if (t < TT) {
                int tn = (t + 1 < TT) ? (t + 1) : (TT - 1);
                load_chunk(tn, 0, c - 16, mg, lane, fh[(c + 2) % 3]);
            }
            compute_chunk(c, fh[c % 3], acc, bf, lane);
        }

        // ---- warp-local epilogue ----
        if (bid < 128) {
            if (t < TT) {
                float hv[4];
                #pragma unroll
                for (int q = 0; q < 4; ++q) {
                    int e = q & 1;
                    float fp = acc[0][q] + bcol[0][e];
                    float ip = acc[1][q] + bcol[1][e];
                    float zp = acc[2][q] + bcol[2][e];
                    float rp = acc[3][q] + bcol[3][e];
                    creg[q] = sg(fp) * creg[q] + sg(ip) * th(rp);
                    hv[q] = sg(zp) * th(creg[q]);
                }
                size_t eo = hstore0 + (size_t)((t + 1) & 1) * (8 * 64 * 32 * 16);
                __stcg((uint2*)((char*)g_hf + eo),
                       make_uint2(pkf16s(hv[0], hv[1]), pkf16s(hv[2], hv[3])));
            }
        } else if (t >= 1) {
            #pragma unroll
            for (int nt = 0; nt < 4; ++nt) {
                int gcol = (bid - 128) * 32 + nt * 8 + tig * 2;
                float2 v0 = make_float2(acc[nt][0] + bcol[nt][0], acc[nt][1] + bcol[nt][1]);
                float2 v1 = make_float2(acc[nt][2] + bcol[nt][0], acc[nt][3] + bcol[nt][1]);
                *(float2*)&y[((size_t)r0 * TT + (t - 1)) * OUTD + gcol] = v0;
                *(float2*)&y[((size_t)r1 * TT + (t - 1)) * OUTD + gcol] = v1;
            }
        }

        __syncthreads();        // all warps' h stores done before arrival
        bar_arrive();           // return-free RED; wait deferred into next step
    }
}

extern "C" void kernel_launch(void* const* d_in, const int* in_sizes, int n_in,
                              void* d_out, int out_size) {
    (void)in_sizes; (void)n_in; (void)out_size;
    cudaFuncSetAttribute(lstm_mma, cudaFuncAttributeMaxDynamicSharedMemorySize, SMEM_TOTAL);
    lstm_mma<<<NCTA, NTHR, SMEM_TOTAL>>>(
        (const float*)d_in[0], (const float*)d_in[1], (const float*)d_in[2],
        (const float*)d_in[3], (const float*)d_in[4], (const float*)d_in[5],
        (const float*)d_in[6], (const float*)d_in[7], (float*)d_out);
}